// round 9
// baseline (speedup 1.0000x reference)
#include <cuda_runtime.h>
#include <cuda_bf16.h>
#include <math.h>

// Problem constants
#define SEQ   2048
#define DIM   4096
#define NH    32
#define NKV   8
#define HD    128
#define KVDIM (NKV * HD)   // 1024

typedef unsigned int u32;

// -------- fp32 scratch --------
__device__ float g_Q[SEQ * DIM];
__device__ float g_K[SEQ * KVDIM];
__device__ float g_V[SEQ * KVDIM];
__device__ float g_attn[SEQ * DIM];

// -------- bf16 split operands (hi + lo residual) --------
__device__ __nv_bfloat16 g_xh[SEQ * DIM],    g_xl[SEQ * DIM];
__device__ __nv_bfloat16 g_wqh[DIM * DIM],   g_wql[DIM * DIM];     // transposed [N][K]
__device__ __nv_bfloat16 g_wkh[KVDIM * DIM], g_wkl[KVDIM * DIM];
__device__ __nv_bfloat16 g_wvh[KVDIM * DIM], g_wvl[KVDIM * DIM];
__device__ __nv_bfloat16 g_woh[DIM * DIM],   g_wol[DIM * DIM];
__device__ __nv_bfloat16 g_ah[SEQ * DIM],    g_al[SEQ * DIM];

// ============================================================================
// Split fp32 -> bf16 hi + bf16 lo(residual). Vectorized x4.
// ============================================================================
__global__ void split_kernel(const float* __restrict__ in,
                             __nv_bfloat16* __restrict__ hi,
                             __nv_bfloat16* __restrict__ lo, int n4)
{
    int i = blockIdx.x * blockDim.x + threadIdx.x;
    if (i >= n4) return;
    float4 v = ((const float4*)in)[i];
    __nv_bfloat162 h01, h23, l01, l23;
    h01.x = __float2bfloat16(v.x); h01.y = __float2bfloat16(v.y);
    h23.x = __float2bfloat16(v.z); h23.y = __float2bfloat16(v.w);
    l01.x = __float2bfloat16(v.x - __bfloat162float(h01.x));
    l01.y = __float2bfloat16(v.y - __bfloat162float(h01.y));
    l23.x = __float2bfloat16(v.z - __bfloat162float(h23.x));
    l23.y = __float2bfloat16(v.w - __bfloat162float(h23.y));
    ((__nv_bfloat162*)hi)[2 * i]     = h01;
    ((__nv_bfloat162*)hi)[2 * i + 1] = h23;
    ((__nv_bfloat162*)lo)[2 * i]     = l01;
    ((__nv_bfloat162*)lo)[2 * i + 1] = l23;
}

// ============================================================================
// Transpose + split: in fp32 [K][N] -> hi/lo bf16 [N][K].
// ============================================================================
__global__ void transpose_split_kernel(const float* __restrict__ in,
                                       __nv_bfloat16* __restrict__ hi,
                                       __nv_bfloat16* __restrict__ lo,
                                       int K, int N)
{
    __shared__ float t[32][33];
    int n0 = blockIdx.x * 32, k0 = blockIdx.y * 32;
    int tx = threadIdx.x, ty = threadIdx.y;   // (32, 8)
    #pragma unroll
    for (int i = 0; i < 4; i++)
        t[ty + i * 8][tx] = in[(size_t)(k0 + ty + i * 8) * N + n0 + tx];
    __syncthreads();
    #pragma unroll
    for (int i = 0; i < 4; i++) {
        float v = t[tx][ty + i * 8];
        __nv_bfloat16 h = __float2bfloat16(v);
        size_t o = (size_t)(n0 + ty + i * 8) * K + k0 + tx;
        hi[o] = h;
        lo[o] = __float2bfloat16(v - __bfloat162float(h));
    }
}

// ============================================================================
// bf16x3-split tensor-core GEMM: C[M,N] fp32 = A @ B^T
//   A: hi/lo bf16 [M][K] row-major;  B: hi/lo bf16 [N][K] row-major (K-major)
// 128x128x32 tiles, 256 threads (8 warps, 4m x 2n), mma.sync.m16n8k16,
// cp.async double-buffered smem, ldmatrix (non-trans) for both operands.
// ============================================================================
#define GBM   128
#define GBN   128
#define GBK   32
#define GLD   40                 // padded row stride in bf16 (conflict-free ldmatrix)
#define GTILE (GBM * GLD)        // bf16 elems per tile buffer
#define GTILEB (GTILE * 2)       // bytes
#define GSMEM (8 * GTILEB)       // 4 matrices x 2 stages = 81920 B

__device__ __forceinline__ void ldsm4(u32* r, u32 addr) {
    asm volatile("ldmatrix.sync.aligned.m8n8.x4.shared.b16 {%0,%1,%2,%3}, [%4];\n"
        : "=r"(r[0]), "=r"(r[1]), "=r"(r[2]), "=r"(r[3]) : "r"(addr));
}
__device__ __forceinline__ void mma16816(float* c, const u32* a, const u32* b) {
    asm volatile("mma.sync.aligned.m16n8k16.row.col.f32.bf16.bf16.f32 "
        "{%0,%1,%2,%3}, {%4,%5,%6,%7}, {%8,%9}, {%0,%1,%2,%3};\n"
        : "+f"(c[0]), "+f"(c[1]), "+f"(c[2]), "+f"(c[3])
        : "r"(a[0]), "r"(a[1]), "r"(a[2]), "r"(a[3]), "r"(b[0]), "r"(b[1]));
}
__device__ __forceinline__ void cp16(u32 dst, const void* src) {
    asm volatile("cp.async.cg.shared.global [%0], [%1], 16;\n" :: "r"(dst), "l"(src));
}

__global__ __launch_bounds__(256) void gemm_bf16x3(
    const __nv_bfloat16* __restrict__ Ah, const __nv_bfloat16* __restrict__ Al,
    const __nv_bfloat16* __restrict__ Bh, const __nv_bfloat16* __restrict__ Bl,
    float* __restrict__ C, int M, int N, int K)
{
    extern __shared__ __nv_bfloat16 smg[];
    __nv_bfloat16* sAh = smg;
    __nv_bfloat16* sAl = sAh + 2 * GTILE;
    __nv_bfloat16* sBh = sAl + 2 * GTILE;
    __nv_bfloat16* sBl = sBh + 2 * GTILE;

    const int tid  = threadIdx.x;
    const int lane = tid & 31;
    const int warp = tid >> 5;
    const int wm   = warp & 3;    // 0..3 -> 32-row slab
    const int wn   = warp >> 2;   // 0..1 -> 64-col slab
    const int m0   = blockIdx.y * GBM;
    const int n0   = blockIdx.x * GBN;

    const u32 sAh0 = (u32)__cvta_generic_to_shared(sAh);
    const u32 sAl0 = (u32)__cvta_generic_to_shared(sAl);
    const u32 sBh0 = (u32)__cvta_generic_to_shared(sBh);
    const u32 sBl0 = (u32)__cvta_generic_to_shared(sBl);

    // global->smem loader: 512 16B-chunks per tile, 2 per thread (rows r, r+64)
    const int lrow = tid >> 2;            // 0..63
    const int lkc  = (tid & 3) * 8;       // bf16 col 0,8,16,24
    const size_t gA = (size_t)(m0 + lrow) * K + lkc;
    const size_t gB = (size_t)(n0 + lrow) * K + lkc;
    const u32 sOff  = (u32)(lrow * GLD + lkc) * 2;
    const u32 sOff2 = sOff + 64 * GLD * 2;

    float acc[2][8][4];
    #pragma unroll
    for (int a = 0; a < 2; a++)
        #pragma unroll
        for (int b = 0; b < 8; b++)
            #pragma unroll
            for (int c = 0; c < 4; c++) acc[a][b][c] = 0.f;

    // ldmatrix fragment byte offsets within a stage
    const u32 aOff = (u32)((wm * 32 + (lane & 15)) * GLD + (lane >> 4) * 8) * 2;
    const u32 bOff = (u32)((wn * 64 + (lane & 7) + ((lane >> 4) & 1) * 8) * GLD
                           + ((lane >> 3) & 1) * 8) * 2;

    const int nk = K / GBK;

    // prologue: stage 0
    {
        cp16(sAh0 + sOff,  Ah + gA);  cp16(sAh0 + sOff2, Ah + gA + (size_t)64 * K);
        cp16(sAl0 + sOff,  Al + gA);  cp16(sAl0 + sOff2, Al + gA + (size_t)64 * K);
        cp16(sBh0 + sOff,  Bh + gB);  cp16(sBh0 + sOff2, Bh + gB + (size_t)64 * K);
        cp16(sBl0 + sOff,  Bl + gB);  cp16(sBl0 + sOff2, Bl + gB + (size_t)64 * K);
        asm volatile("cp.async.commit_group;\n");
    }

    for (int it = 0; it < nk; it++) {
        if (it + 1 < nk) {
            const int kk = (it + 1) * GBK;
            const u32 sb = (u32)(((it + 1) & 1) * GTILEB);
            cp16(sAh0 + sb + sOff,  Ah + gA + kk);
            cp16(sAh0 + sb + sOff2, Ah + gA + kk + (size_t)64 * K);
            cp16(sAl0 + sb + sOff,  Al + gA + kk);
            cp16(sAl0 + sb + sOff2, Al + gA + kk + (size_t)64 * K);
            cp16(sBh0 + sb + sOff,  Bh + gB + kk);
            cp16(sBh0 + sb + sOff2, Bh + gB + kk + (size_t)64 * K);
            cp16(sBl0 + sb + sOff,  Bl + gB + kk);
            cp16(sBl0 + sb + sOff2, Bl + gB + kk + (size_t)64 * K);
            asm volatile("cp.async.commit_group;\n");
            asm volatile("cp.async.wait_group 1;\n");
        } else {
            asm volatile("cp.async.wait_group 0;\n");
        }
        __syncthreads();

        const u32 sb = (u32)((it & 1) * GTILEB);
        #pragma unroll
        for (int ks = 0; ks < 2; ks++) {
            const u32 kb = sb + ks * 32;    // k16 step = 32 bytes
            u32 a_hi[2][4], a_lo[2][4], b_hi[4][4], b_lo[4][4];
            #pragma unroll
            for (int mt = 0; mt < 2; mt++) {
                ldsm4(a_hi[mt], sAh0 + kb + aOff + mt * (16 * GLD * 2));
                ldsm4(a_lo[mt], sAl0 + kb + aOff + mt * (16 * GLD * 2));
            }
            #pragma unroll
            for (int np = 0; np < 4; np++) {
                ldsm4(b_hi[np], sBh0 + kb + bOff + np * (16 * GLD * 2));
                ldsm4(b_lo[np], sBl0 + kb + bOff + np * (16 * GLD * 2));
            }
            #pragma unroll
            for (int mt = 0; mt < 2; mt++)
                #pragma unroll
                for (int nt = 0; nt < 8; nt++) {
                    const u32* bh = &b_hi[nt >> 1][(nt & 1) * 2];
                    const u32* bl = &b_lo[nt >> 1][(nt & 1) * 2];
                    mma16816(acc[mt][nt], a_hi[mt], bh);
                    mma16816(acc[mt][nt], a_lo[mt], bh);
                    mma16816(acc[mt][nt], a_hi[mt], bl);
                }
        }
        __syncthreads();
    }

    // epilogue: fragment -> fp32 global
    const int erow = m0 + wm * 32 + (lane >> 2);
    const int ecol = n0 + wn * 64 + (lane & 3) * 2;
    #pragma unroll
    for (int mt = 0; mt < 2; mt++)
        #pragma unroll
        for (int nt = 0; nt < 8; nt++) {
            int r = erow + mt * 16;
            int c = ecol + nt * 8;
            *(float2*)&C[(size_t)r * N + c] =
                make_float2(acc[mt][nt][0], acc[mt][nt][1]);
            *(float2*)&C[(size_t)(r + 8) * N + c] =
                make_float2(acc[mt][nt][2], acc[mt][nt][3]);
        }
}

// ============================================================================
// RoPE (interleaved pairs), optional scale folded in.
// ============================================================================
__global__ void rope_kernel(float* __restrict__ t, int n_heads, float scale)
{
    int idx = blockIdx.x * blockDim.x + threadIdx.x;
    int total = SEQ * n_heads * (HD / 2);
    if (idx >= total) return;
    int i   = idx & 63;
    int h   = (idx >> 6) % n_heads;
    int pos = idx / (64 * n_heads);

    float inv = powf(10000.0f, -(float)(2 * i) / 128.0f);
    float ang = (float)pos * inv;
    float s, c;
    sincosf(ang, &s, &c);

    float* p = t + ((size_t)pos * n_heads + h) * HD + 2 * i;
    float a = p[0], b = p[1];
    p[0] = (a * c - b * s) * scale;
    p[1] = (a * s + b * c) * scale;
}

// ============================================================================
// Flash-style causal GQA attention, fp32 (unchanged from R7-passing version).
// ============================================================================
#define PS 68

__global__ __launch_bounds__(256) void attn_kernel()
{
    extern __shared__ float sm[];
    float* Qs  = sm;
    float* Kst = Qs  + 64 * 128;
    float* Vs  = Kst + 128 * 64;
    float* Ps  = Vs  + 64 * 128;

    const int tid = threadIdx.x;
    const int tx  = tid & 15;
    const int ty  = tid >> 4;
    const int qb  = blockIdx.x;
    const int h   = blockIdx.y;
    const int kvh = h >> 2;

    for (int f = tid; f < 64 * 32; f += 256) {
        int r = f >> 5, c = (f & 31) << 2;
        *(float4*)&Qs[r * 128 + c] =
            *(const float4*)&g_Q[((size_t)(qb * 64 + r)) * DIM + h * HD + c];
    }

    float m[4], l[4], acc[4][8];
    #pragma unroll
    for (int a = 0; a < 4; a++) {
        m[a] = -1e30f; l[a] = 0.f;
        #pragma unroll
        for (int j = 0; j < 8; j++) acc[a][j] = 0.f;
    }

    const int kc  = tid >> 2;
    const int kd0 = (tid & 3) << 5;

    for (int j = 0; j <= qb; j++) {
        __syncthreads();
        {
            const float* kg = g_K + ((size_t)(j * 64 + kc)) * KVDIM + kvh * HD + kd0;
            #pragma unroll
            for (int q = 0; q < 8; q++) {
                float4 v = *(const float4*)(kg + q * 4);
                int d = kd0 + q * 4;
                Kst[(d + 0) * 64 + kc] = v.x;
                Kst[(d + 1) * 64 + kc] = v.y;
                Kst[(d + 2) * 64 + kc] = v.z;
                Kst[(d + 3) * 64 + kc] = v.w;
            }
        }
        for (int f = tid; f < 64 * 32; f += 256) {
            int r = f >> 5, c = (f & 31) << 2;
            *(float4*)&Vs[r * 128 + c] =
                *(const float4*)&g_V[((size_t)(j * 64 + r)) * KVDIM + kvh * HD + c];
        }
        __syncthreads();

        float s[4][4];
        #pragma unroll
        for (int a = 0; a < 4; a++)
            #pragma unroll
            for (int b = 0; b < 4; b++) s[a][b] = 0.f;

        for (int d = 0; d < 128; d += 4) {
            float4 k0 = *(float4*)&Kst[(d + 0) * 64 + tx * 4];
            float4 k1 = *(float4*)&Kst[(d + 1) * 64 + tx * 4];
            float4 k2 = *(float4*)&Kst[(d + 2) * 64 + tx * 4];
            float4 k3 = *(float4*)&Kst[(d + 3) * 64 + tx * 4];
            #pragma unroll
            for (int a = 0; a < 4; a++) {
                float4 q4 = *(float4*)&Qs[(ty * 4 + a) * 128 + d];
                s[a][0] += q4.x * k0.x + q4.y * k1.x + q4.z * k2.x + q4.w * k3.x;
                s[a][1] += q4.x * k0.y + q4.y * k1.y + q4.z * k2.y + q4.w * k3.y;
                s[a][2] += q4.x * k0.z + q4.y * k1.z + q4.z * k2.z + q4.w * k3.z;
                s[a][3] += q4.x * k0.w + q4.y * k1.w + q4.z * k2.w + q4.w * k3.w;
            }
        }

        if (j == qb) {
            #pragma unroll
            for (int a = 0; a < 4; a++) {
                int qr = ty * 4 + a;
                #pragma unroll
                for (int b = 0; b < 4; b++)
                    if (tx * 4 + b > qr) s[a][b] = -1e30f;
            }
        }

        #pragma unroll
        for (int a = 0; a < 4; a++) {
            float rm = fmaxf(fmaxf(s[a][0], s[a][1]), fmaxf(s[a][2], s[a][3]));
            #pragma unroll
            for (int o = 8; o > 0; o >>= 1)
                rm = fmaxf(rm, __shfl_xor_sync(0xffffffffu, rm, o));
            float mn   = fmaxf(m[a], rm);
            float corr = __expf(m[a] - mn);
            float p0 = __expf(s[a][0] - mn);
            float p1 = __expf(s[a][1] - mn);
            float p2 = __expf(s[a][2] - mn);
            float p3 = __expf(s[a][3] - mn);
            float ps = p0 + p1 + p2 + p3;
            #pragma unroll
            for (int o = 8; o > 0; o >>= 1)
                ps += __shfl_xor_sync(0xffffffffu, ps, o);
            l[a] = l[a] * corr + ps;
            m[a] = mn;
            #pragma unroll
            for (int jj = 0; jj < 8; jj++) acc[a][jj] *= corr;
            *(float4*)&Ps[(ty * 4 + a) * PS + tx * 4] = make_float4(p0, p1, p2, p3);
        }
        __syncthreads();

        for (int c = 0; c < 64; c += 4) {
            float4 pr[4];
            #pragma unroll
            for (int a = 0; a < 4; a++)
                pr[a] = *(float4*)&Ps[(ty * 4 + a) * PS + c];
            #pragma unroll
            for (int cc = 0; cc < 4; cc++) {
                float4 v0 = *(float4*)&Vs[(c + cc) * 128 + tx * 4];
                float4 v1 = *(float4*)&Vs[(c + cc) * 128 + 64 + tx * 4];
                #pragma unroll
                for (int a = 0; a < 4; a++) {
                    float p = (cc == 0) ? pr[a].x : (cc == 1) ? pr[a].y
                            : (cc == 2) ? pr[a].z : pr[a].w;
                    acc[a][0] += p * v0.x; acc[a][1] += p * v0.y;
                    acc[a][2] += p * v0.z; acc[a][3] += p * v0.w;
                    acc[a][4] += p * v1.x; acc[a][5] += p * v1.y;
                    acc[a][6] += p * v1.z; acc[a][7] += p * v1.w;
                }
            }
        }
    }

    #pragma unroll
    for (int a = 0; a < 4; a++) {
        float inv = 1.0f / l[a];
        int row = qb * 64 + ty * 4 + a;
        float* o = g_attn + (size_t)row * DIM + h * HD;
        *(float4*)(o + tx * 4) =
            make_float4(acc[a][0] * inv, acc[a][1] * inv, acc[a][2] * inv, acc[a][3] * inv);
        *(float4*)(o + 64 + tx * 4) =
            make_float4(acc[a][4] * inv, acc[a][5] * inv, acc[a][6] * inv, acc[a][7] * inv);
    }
}

#define ATT_SMEM ((64 * 128 * 3 + 64 * PS) * (int)sizeof(float))

// ============================================================================
// kernel_launch
// ============================================================================
extern "C" void kernel_launch(void* const* d_in, const int* in_sizes, int n_in,
                              void* d_out, int out_size)
{
    const float* x  = (const float*)d_in[0];
    const float* wq = (const float*)d_in[1];
    const float* wk = (const float*)d_in[2];
    const float* wv = (const float*)d_in[3];
    const float* wo = (const float*)d_in[4];
    float* out = (float*)d_out;

    float *Q, *K, *V, *ATT;
    cudaGetSymbolAddress((void**)&Q,   g_Q);
    cudaGetSymbolAddress((void**)&K,   g_K);
    cudaGetSymbolAddress((void**)&V,   g_V);
    cudaGetSymbolAddress((void**)&ATT, g_attn);

    __nv_bfloat16 *xh, *xl, *wqh, *wql, *wkh, *wkl, *wvh, *wvl, *woh, *wol, *ah, *al;
    cudaGetSymbolAddress((void**)&xh,  g_xh);  cudaGetSymbolAddress((void**)&xl,  g_xl);
    cudaGetSymbolAddress((void**)&wqh, g_wqh); cudaGetSymbolAddress((void**)&wql, g_wql);
    cudaGetSymbolAddress((void**)&wkh, g_wkh); cudaGetSymbolAddress((void**)&wkl, g_wkl);
    cudaGetSymbolAddress((void**)&wvh, g_wvh); cudaGetSymbolAddress((void**)&wvl, g_wvl);
    cudaGetSymbolAddress((void**)&woh, g_woh); cudaGetSymbolAddress((void**)&wol, g_wol);
    cudaGetSymbolAddress((void**)&ah,  g_ah);  cudaGetSymbolAddress((void**)&al,  g_al);

    cudaFuncSetAttribute(gemm_bf16x3,
                         cudaFuncAttributeMaxDynamicSharedMemorySize, GSMEM);
    cudaFuncSetAttribute(attn_kernel,
                         cudaFuncAttributeMaxDynamicSharedMemorySize, ATT_SMEM);

    // 1) split x; transpose+split weights
    split_kernel<<<(SEQ * DIM / 4 + 255) / 256, 256>>>(x, xh, xl, SEQ * DIM / 4);
    transpose_split_kernel<<<dim3(DIM   / 32, DIM / 32), dim3(32, 8)>>>(wq, wqh, wql, DIM, DIM);
    transpose_split_kernel<<<dim3(KVDIM / 32, DIM / 32), dim3(32, 8)>>>(wk, wkh, wkl, DIM, KVDIM);
    transpose_split_kernel<<<dim3(KVDIM / 32, DIM / 32), dim3(32, 8)>>>(wv, wvh, wvl, DIM, KVDIM);
    transpose_split_kernel<<<dim3(DIM   / 32, DIM / 32), dim3(32, 8)>>>(wo, woh, wol, DIM, DIM);

    // 2) QKV projections (tensor cores)
    gemm_bf16x3<<<dim3(DIM   / GBN, SEQ / GBM), 256, GSMEM>>>(xh, xl, wqh, wql, Q, SEQ, DIM,   DIM);
    gemm_bf16x3<<<dim3(KVDIM / GBN, SEQ / GBM), 256, GSMEM>>>(xh, xl, wkh, wkl, K, SEQ, KVDIM, DIM);
    gemm_bf16x3<<<dim3(KVDIM / GBN, SEQ / GBM), 256, GSMEM>>>(xh, xl, wvh, wvl, V, SEQ, KVDIM, DIM);

    // 3) RoPE (fold 1/sqrt(HD) into Q)
    const float scale = 0.08838834764831845f;
    int nq = SEQ * NH  * (HD / 2);
    int nk = SEQ * NKV * (HD / 2);
    rope_kernel<<<(nq + 255) / 256, 256>>>(Q, NH,  scale);
    rope_kernel<<<(nk + 255) / 256, 256>>>(K, NKV, 1.0f);

    // 4) attention
    attn_kernel<<<dim3(SEQ / 64, NH), 256, ATT_SMEM>>>();

    // 5) output projection
    split_kernel<<<(SEQ * DIM / 4 + 255) / 256, 256>>>(ATT, ah, al, SEQ * DIM / 4);
    gemm_bf16x3<<<dim3(DIM / GBN, SEQ / GBM), 256, GSMEM>>>(ah, al, woh, wol, out, SEQ, DIM, DIM);
}

// round 10
// speedup vs baseline: 1.3241x; 1.3241x over previous
#include <cuda_runtime.h>
#include <cuda_bf16.h>
#include <math.h>

// Problem constants
#define SEQ   2048
#define DIM   4096
#define NH    32
#define NKV   8
#define HD    128
#define KVDIM (NKV * HD)   // 1024

typedef unsigned int u32;

// -------- fp32 scratch --------
__device__ float g_Q[SEQ * DIM];
__device__ float g_K[SEQ * KVDIM];
__device__ float g_V[SEQ * KVDIM];
__device__ float g_attn[SEQ * DIM];

// -------- bf16 split operands (hi + lo residual) --------
__device__ __nv_bfloat16 g_xh[SEQ * DIM],    g_xl[SEQ * DIM];
__device__ __nv_bfloat16 g_wqh[DIM * DIM],   g_wql[DIM * DIM];     // transposed [N][K]
__device__ __nv_bfloat16 g_wkh[KVDIM * DIM], g_wkl[KVDIM * DIM];
__device__ __nv_bfloat16 g_wvh[KVDIM * DIM], g_wvl[KVDIM * DIM];
__device__ __nv_bfloat16 g_woh[DIM * DIM],   g_wol[DIM * DIM];
__device__ __nv_bfloat16 g_ah[SEQ * DIM],    g_al[SEQ * DIM];
// bf16 split Q/K/V for tensor-core attention
__device__ __nv_bfloat16 g_qbh[SEQ * DIM],   g_qbl[SEQ * DIM];
__device__ __nv_bfloat16 g_kbh[SEQ * KVDIM], g_kbl[SEQ * KVDIM];
__device__ __nv_bfloat16 g_vbh[SEQ * KVDIM], g_vbl[SEQ * KVDIM];

// ============================================================================
// Split fp32 -> bf16 hi + bf16 lo(residual). Vectorized x4.
// ============================================================================
__global__ void split_kernel(const float* __restrict__ in,
                             __nv_bfloat16* __restrict__ hi,
                             __nv_bfloat16* __restrict__ lo, int n4)
{
    int i = blockIdx.x * blockDim.x + threadIdx.x;
    if (i >= n4) return;
    float4 v = ((const float4*)in)[i];
    __nv_bfloat162 h01, h23, l01, l23;
    h01.x = __float2bfloat16(v.x); h01.y = __float2bfloat16(v.y);
    h23.x = __float2bfloat16(v.z); h23.y = __float2bfloat16(v.w);
    l01.x = __float2bfloat16(v.x - __bfloat162float(h01.x));
    l01.y = __float2bfloat16(v.y - __bfloat162float(h01.y));
    l23.x = __float2bfloat16(v.z - __bfloat162float(h23.x));
    l23.y = __float2bfloat16(v.w - __bfloat162float(h23.y));
    ((__nv_bfloat162*)hi)[2 * i]     = h01;
    ((__nv_bfloat162*)hi)[2 * i + 1] = h23;
    ((__nv_bfloat162*)lo)[2 * i]     = l01;
    ((__nv_bfloat162*)lo)[2 * i + 1] = l23;
}

// ============================================================================
// Transpose + split: in fp32 [K][N] -> hi/lo bf16 [N][K].
// ============================================================================
__global__ void transpose_split_kernel(const float* __restrict__ in,
                                       __nv_bfloat16* __restrict__ hi,
                                       __nv_bfloat16* __restrict__ lo,
                                       int K, int N)
{
    __shared__ float t[32][33];
    int n0 = blockIdx.x * 32, k0 = blockIdx.y * 32;
    int tx = threadIdx.x, ty = threadIdx.y;   // (32, 8)
    #pragma unroll
    for (int i = 0; i < 4; i++)
        t[ty + i * 8][tx] = in[(size_t)(k0 + ty + i * 8) * N + n0 + tx];
    __syncthreads();
    #pragma unroll
    for (int i = 0; i < 4; i++) {
        float v = t[tx][ty + i * 8];
        __nv_bfloat16 h = __float2bfloat16(v);
        size_t o = (size_t)(n0 + ty + i * 8) * K + k0 + tx;
        hi[o] = h;
        lo[o] = __float2bfloat16(v - __bfloat162float(h));
    }
}

// ============================================================================
// MMA / ldmatrix / cp.async primitives
// ============================================================================
__device__ __forceinline__ void ldsm4(u32* r, u32 addr) {
    asm volatile("ldmatrix.sync.aligned.m8n8.x4.shared.b16 {%0,%1,%2,%3}, [%4];\n"
        : "=r"(r[0]), "=r"(r[1]), "=r"(r[2]), "=r"(r[3]) : "r"(addr));
}
__device__ __forceinline__ void ldsm4t(u32* r, u32 addr) {
    asm volatile("ldmatrix.sync.aligned.m8n8.x4.trans.shared.b16 {%0,%1,%2,%3}, [%4];\n"
        : "=r"(r[0]), "=r"(r[1]), "=r"(r[2]), "=r"(r[3]) : "r"(addr));
}
__device__ __forceinline__ void mma16816(float* c, const u32* a, const u32* b) {
    asm volatile("mma.sync.aligned.m16n8k16.row.col.f32.bf16.bf16.f32 "
        "{%0,%1,%2,%3}, {%4,%5,%6,%7}, {%8,%9}, {%0,%1,%2,%3};\n"
        : "+f"(c[0]), "+f"(c[1]), "+f"(c[2]), "+f"(c[3])
        : "r"(a[0]), "r"(a[1]), "r"(a[2]), "r"(a[3]), "r"(b[0]), "r"(b[1]));
}
__device__ __forceinline__ void cp16(u32 dst, const void* src) {
    asm volatile("cp.async.cg.shared.global [%0], [%1], 16;\n" :: "r"(dst), "l"(src));
}

// ============================================================================
// bf16x3-split tensor-core GEMM (unchanged from R8 passing version)
// ============================================================================
#define GBM   128
#define GBN   128
#define GBK   32
#define GLD   40
#define GTILE (GBM * GLD)
#define GTILEB (GTILE * 2)
#define GSMEM (8 * GTILEB)

__global__ __launch_bounds__(256) void gemm_bf16x3(
    const __nv_bfloat16* __restrict__ Ah, const __nv_bfloat16* __restrict__ Al,
    const __nv_bfloat16* __restrict__ Bh, const __nv_bfloat16* __restrict__ Bl,
    float* __restrict__ C, int M, int N, int K)
{
    extern __shared__ __nv_bfloat16 smg[];
    __nv_bfloat16* sAh = smg;
    __nv_bfloat16* sAl = sAh + 2 * GTILE;
    __nv_bfloat16* sBh = sAl + 2 * GTILE;
    __nv_bfloat16* sBl = sBh + 2 * GTILE;

    const int tid  = threadIdx.x;
    const int lane = tid & 31;
    const int warp = tid >> 5;
    const int wm   = warp & 3;
    const int wn   = warp >> 2;
    const int m0   = blockIdx.y * GBM;
    const int n0   = blockIdx.x * GBN;

    const u32 sAh0 = (u32)__cvta_generic_to_shared(sAh);
    const u32 sAl0 = (u32)__cvta_generic_to_shared(sAl);
    const u32 sBh0 = (u32)__cvta_generic_to_shared(sBh);
    const u32 sBl0 = (u32)__cvta_generic_to_shared(sBl);

    const int lrow = tid >> 2;
    const int lkc  = (tid & 3) * 8;
    const size_t gA = (size_t)(m0 + lrow) * K + lkc;
    const size_t gB = (size_t)(n0 + lrow) * K + lkc;
    const u32 sOff  = (u32)(lrow * GLD + lkc) * 2;
    const u32 sOff2 = sOff + 64 * GLD * 2;

    float acc[2][8][4];
    #pragma unroll
    for (int a = 0; a < 2; a++)
        #pragma unroll
        for (int b = 0; b < 8; b++)
            #pragma unroll
            for (int c = 0; c < 4; c++) acc[a][b][c] = 0.f;

    const u32 aOff = (u32)((wm * 32 + (lane & 15)) * GLD + (lane >> 4) * 8) * 2;
    const u32 bOff = (u32)((wn * 64 + (lane & 7) + ((lane >> 4) & 1) * 8) * GLD
                           + ((lane >> 3) & 1) * 8) * 2;

    const int nk = K / GBK;

    {
        cp16(sAh0 + sOff,  Ah + gA);  cp16(sAh0 + sOff2, Ah + gA + (size_t)64 * K);
        cp16(sAl0 + sOff,  Al + gA);  cp16(sAl0 + sOff2, Al + gA + (size_t)64 * K);
        cp16(sBh0 + sOff,  Bh + gB);  cp16(sBh0 + sOff2, Bh + gB + (size_t)64 * K);
        cp16(sBl0 + sOff,  Bl + gB);  cp16(sBl0 + sOff2, Bl + gB + (size_t)64 * K);
        asm volatile("cp.async.commit_group;\n");
    }

    for (int it = 0; it < nk; it++) {
        if (it + 1 < nk) {
            const int kk = (it + 1) * GBK;
            const u32 sb = (u32)(((it + 1) & 1) * GTILEB);
            cp16(sAh0 + sb + sOff,  Ah + gA + kk);
            cp16(sAh0 + sb + sOff2, Ah + gA + kk + (size_t)64 * K);
            cp16(sAl0 + sb + sOff,  Al + gA + kk);
            cp16(sAl0 + sb + sOff2, Al + gA + kk + (size_t)64 * K);
            cp16(sBh0 + sb + sOff,  Bh + gB + kk);
            cp16(sBh0 + sb + sOff2, Bh + gB + kk + (size_t)64 * K);
            cp16(sBl0 + sb + sOff,  Bl + gB + kk);
            cp16(sBl0 + sb + sOff2, Bl + gB + kk + (size_t)64 * K);
            asm volatile("cp.async.commit_group;\n");
            asm volatile("cp.async.wait_group 1;\n");
        } else {
            asm volatile("cp.async.wait_group 0;\n");
        }
        __syncthreads();

        const u32 sb = (u32)((it & 1) * GTILEB);
        #pragma unroll
        for (int ks = 0; ks < 2; ks++) {
            const u32 kb = sb + ks * 32;
            u32 a_hi[2][4], a_lo[2][4], b_hi[4][4], b_lo[4][4];
            #pragma unroll
            for (int mt = 0; mt < 2; mt++) {
                ldsm4(a_hi[mt], sAh0 + kb + aOff + mt * (16 * GLD * 2));
                ldsm4(a_lo[mt], sAl0 + kb + aOff + mt * (16 * GLD * 2));
            }
            #pragma unroll
            for (int np = 0; np < 4; np++) {
                ldsm4(b_hi[np], sBh0 + kb + bOff + np * (16 * GLD * 2));
                ldsm4(b_lo[np], sBl0 + kb + bOff + np * (16 * GLD * 2));
            }
            #pragma unroll
            for (int mt = 0; mt < 2; mt++)
                #pragma unroll
                for (int nt = 0; nt < 8; nt++) {
                    const u32* bh = &b_hi[nt >> 1][(nt & 1) * 2];
                    const u32* bl = &b_lo[nt >> 1][(nt & 1) * 2];
                    mma16816(acc[mt][nt], a_hi[mt], bh);
                    mma16816(acc[mt][nt], a_lo[mt], bh);
                    mma16816(acc[mt][nt], a_hi[mt], bl);
                }
        }
        __syncthreads();
    }

    const int erow = m0 + wm * 32 + (lane >> 2);
    const int ecol = n0 + wn * 64 + (lane & 3) * 2;
    #pragma unroll
    for (int mt = 0; mt < 2; mt++)
        #pragma unroll
        for (int nt = 0; nt < 8; nt++) {
            int r = erow + mt * 16;
            int c = ecol + nt * 8;
            *(float2*)&C[(size_t)r * N + c] =
                make_float2(acc[mt][nt][0], acc[mt][nt][1]);
            *(float2*)&C[(size_t)(r + 8) * N + c] =
                make_float2(acc[mt][nt][2], acc[mt][nt][3]);
        }
}

// ============================================================================
// RoPE + bf16 hi/lo split: reads fp32 [SEQ][n_heads][128], writes split bf16.
// ============================================================================
__global__ void rope_split_kernel(const float* __restrict__ src,
                                  __nv_bfloat16* __restrict__ hi,
                                  __nv_bfloat16* __restrict__ lo,
                                  int n_heads, float scale)
{
    int idx = blockIdx.x * blockDim.x + threadIdx.x;
    int total = SEQ * n_heads * (HD / 2);
    if (idx >= total) return;
    int i   = idx & 63;
    int h   = (idx >> 6) % n_heads;
    int pos = idx / (64 * n_heads);

    float inv = powf(10000.0f, -(float)(2 * i) / 128.0f);
    float ang = (float)pos * inv;
    float s, c;
    sincosf(ang, &s, &c);

    size_t off = ((size_t)pos * n_heads + h) * HD + 2 * i;
    const float* p = src + off;
    float a = p[0], b = p[1];
    float o0 = (a * c - b * s) * scale;
    float o1 = (a * s + b * c) * scale;

    __nv_bfloat162 hh, ll;
    hh.x = __float2bfloat16(o0);
    hh.y = __float2bfloat16(o1);
    ll.x = __float2bfloat16(o0 - __bfloat162float(hh.x));
    ll.y = __float2bfloat16(o1 - __bfloat162float(hh.y));
    ((__nv_bfloat162*)hi)[off >> 1] = hh;
    ((__nv_bfloat162*)lo)[off >> 1] = ll;
}

// ============================================================================
// Tensor-core flash attention (causal, GQA), bf16x3-split.
// grid = (SEQ/64, NH), 128 threads (4 warps, warp w owns q-rows w*16..+15).
// S = Qh*Kh + Ql*Kh + Qh*Kl; P split into hi/lo in registers (FA2 reuse);
// O += Ph*Vh + Pl*Vh + Ph*Vl.  V loaded via ldmatrix.trans.
// ============================================================================
#define LDB   136                     // bf16 row stride (128 + 8 pad)
#define ATILE (64 * LDB)              // elems per smem tile
#define ASMEM (6 * ATILE * 2)         // 6 tiles (Qh,Ql,Kh,Kl,Vh,Vl) = 104448 B

__global__ __launch_bounds__(128) void attn_mma(
    const __nv_bfloat16* __restrict__ Qh, const __nv_bfloat16* __restrict__ Ql,
    const __nv_bfloat16* __restrict__ Kh, const __nv_bfloat16* __restrict__ Kl,
    const __nv_bfloat16* __restrict__ Vh, const __nv_bfloat16* __restrict__ Vl)
{
    extern __shared__ __nv_bfloat16 sma[];
    const u32 sQh = (u32)__cvta_generic_to_shared(sma);
    const u32 sQl = sQh + ATILE * 2;
    const u32 sKh = sQl + ATILE * 2;
    const u32 sKl = sKh + ATILE * 2;
    const u32 sVh = sKl + ATILE * 2;
    const u32 sVl = sVh + ATILE * 2;

    const int tid  = threadIdx.x;
    const int lane = tid & 31;
    const int warp = tid >> 5;
    const int qb   = blockIdx.x;
    const int h    = blockIdx.y;
    const int kvh  = h >> 2;            // N_REP = 4
    const int g    = lane >> 2;         // row-in-fragment 0..7
    const int tig  = lane & 3;          // thread-in-group

    // ---- loader geometry: row = tid>>1, half = tid&1 (64 bf16 = 8 x 16B) ----
    const int lrow  = tid >> 1;
    const int lhalf = (tid & 1) * 64;
    const u32 sOff  = (u32)(lrow * LDB + lhalf) * 2;

    // Q tile (persistent in smem)
    {
        size_t qo = ((size_t)(qb * 64 + lrow) * NH + h) * HD + lhalf;
        #pragma unroll
        for (int c = 0; c < 8; c++) {
            cp16(sQh + sOff + c * 16, Qh + qo + c * 8);
            cp16(sQl + sOff + c * 16, Ql + qo + c * 8);
        }
        asm volatile("cp.async.commit_group;\n");
    }

    // ---- fragment addresses ----
    const u32 aO = (u32)((warp * 16 + (lane & 15)) * LDB) * 2 + (lane >> 4) * 16;
    const u32 bO = (u32)(((lane & 7) + ((lane >> 4) & 1) * 8) * LDB) * 2
                 + ((lane >> 3) & 1) * 16;
    const u32 vO = (u32)((lane & 15) * LDB) * 2 + (lane >> 4) * 16;

    float m[2] = {-1e30f, -1e30f}, l[2] = {0.f, 0.f};
    float acc[16][4];
    #pragma unroll
    for (int nt = 0; nt < 16; nt++)
        #pragma unroll
        for (int c = 0; c < 4; c++) acc[nt][c] = 0.f;

    for (int j = 0; j <= qb; j++) {
        __syncthreads();   // previous iteration's K/V reads complete
        {
            size_t ko = ((size_t)(j * 64 + lrow) * NKV + kvh) * HD + lhalf;
            #pragma unroll
            for (int c = 0; c < 8; c++) {
                cp16(sKh + sOff + c * 16, Kh + ko + c * 8);
                cp16(sKl + sOff + c * 16, Kl + ko + c * 8);
                cp16(sVh + sOff + c * 16, Vh + ko + c * 8);
                cp16(sVl + sOff + c * 16, Vl + ko + c * 8);
            }
            asm volatile("cp.async.commit_group;\n");
            asm volatile("cp.async.wait_group 0;\n");
        }
        __syncthreads();

        // ---- S = Q @ K^T (bf16x3), per-warp m16 x n64, k = 128 ----
        float sv[8][4];
        #pragma unroll
        for (int nt = 0; nt < 8; nt++)
            #pragma unroll
            for (int c = 0; c < 4; c++) sv[nt][c] = 0.f;

        #pragma unroll
        for (int ks = 0; ks < 8; ks++) {
            const u32 kb = ks * 32;
            u32 ah[4], al[4];
            ldsm4(ah, sQh + aO + kb);
            ldsm4(al, sQl + aO + kb);
            #pragma unroll
            for (int np = 0; np < 4; np++) {
                u32 bh[4], bl[4];
                ldsm4(bh, sKh + bO + np * (16 * LDB * 2) + kb);
                ldsm4(bl, sKl + bO + np * (16 * LDB * 2) + kb);
                mma16816(sv[2 * np],     ah, &bh[0]);
                mma16816(sv[2 * np],     al, &bh[0]);
                mma16816(sv[2 * np],     ah, &bl[0]);
                mma16816(sv[2 * np + 1], ah, &bh[2]);
                mma16816(sv[2 * np + 1], al, &bh[2]);
                mma16816(sv[2 * np + 1], ah, &bl[2]);
            }
        }

        // ---- causal mask on diagonal block ----
        if (j == qb) {
            #pragma unroll
            for (int nt = 0; nt < 8; nt++)
                #pragma unroll
                for (int c = 0; c < 4; c++) {
                    int col = nt * 8 + tig * 2 + (c & 1);
                    int row = warp * 16 + g + (c >> 1) * 8;
                    if (col > row) sv[nt][c] = -1e30f;
                }
        }

        // ---- online softmax (rows g and g+8; groups of 4 lanes per row) ----
        #pragma unroll
        for (int half = 0; half < 2; half++) {
            float rm = -1e30f;
            #pragma unroll
            for (int nt = 0; nt < 8; nt++)
                rm = fmaxf(rm, fmaxf(sv[nt][half * 2], sv[nt][half * 2 + 1]));
            rm = fmaxf(rm, __shfl_xor_sync(0xffffffffu, rm, 1));
            rm = fmaxf(rm, __shfl_xor_sync(0xffffffffu, rm, 2));
            float mn   = fmaxf(m[half], rm);
            float corr = __expf(m[half] - mn);
            float rs = 0.f;
            #pragma unroll
            for (int nt = 0; nt < 8; nt++) {
                float p0 = __expf(sv[nt][half * 2]     - mn);
                float p1 = __expf(sv[nt][half * 2 + 1] - mn);
                sv[nt][half * 2]     = p0;
                sv[nt][half * 2 + 1] = p1;
                rs += p0 + p1;
            }
            rs += __shfl_xor_sync(0xffffffffu, rs, 1);
            rs += __shfl_xor_sync(0xffffffffu, rs, 2);
            l[half] = l[half] * corr + rs;
            m[half] = mn;
            #pragma unroll
            for (int nt = 0; nt < 16; nt++) {
                acc[nt][half * 2]     *= corr;
                acc[nt][half * 2 + 1] *= corr;
            }
        }
        __syncwarp();

        // ---- O += P @ V (bf16x3), P fragments built from sv in registers ----
        #pragma unroll
        for (int ks = 0; ks < 4; ks++) {
            u32 pa_h[4], pa_l[4];
            #pragma unroll
            for (int t = 0; t < 2; t++) {
                float p0 = sv[2 * ks + t][0], p1 = sv[2 * ks + t][1];
                float p2 = sv[2 * ks + t][2], p3 = sv[2 * ks + t][3];
                __nv_bfloat162 h01, h23, l01, l23;
                h01.x = __float2bfloat16(p0); h01.y = __float2bfloat16(p1);
                h23.x = __float2bfloat16(p2); h23.y = __float2bfloat16(p3);
                l01.x = __float2bfloat16(p0 - __bfloat162float(h01.x));
                l01.y = __float2bfloat16(p1 - __bfloat162float(h01.y));
                l23.x = __float2bfloat16(p2 - __bfloat162float(h23.x));
                l23.y = __float2bfloat16(p3 - __bfloat162float(h23.y));
                pa_h[2 * t]     = *(u32*)&h01;  // a0/a2: row g
                pa_h[2 * t + 1] = *(u32*)&h23;  // a1/a3: row g+8
                pa_l[2 * t]     = *(u32*)&l01;
                pa_l[2 * t + 1] = *(u32*)&l23;
            }
            const u32 kb = (u32)(ks * 16 * LDB) * 2;
            #pragma unroll
            for (int np = 0; np < 8; np++) {
                u32 vh[4], vl[4];
                ldsm4t(vh, sVh + vO + kb + np * 32);
                ldsm4t(vl, sVl + vO + kb + np * 32);
                mma16816(acc[2 * np],     pa_h, &vh[0]);
                mma16816(acc[2 * np],     pa_l, &vh[0]);
                mma16816(acc[2 * np],     pa_h, &vl[0]);
                mma16816(acc[2 * np + 1], pa_h, &vh[2]);
                mma16816(acc[2 * np + 1], pa_l, &vh[2]);
                mma16816(acc[2 * np + 1], pa_h, &vl[2]);
            }
        }
    }

    // ---- epilogue: normalize, write fp32 [SEQ][NH*HD] ----
    #pragma unroll
    for (int half = 0; half < 2; half++) {
        float inv = 1.0f / l[half];
        int row = qb * 64 + warp * 16 + g + half * 8;
        float* o = g_attn + (size_t)row * DIM + h * HD;
        #pragma unroll
        for (int nt = 0; nt < 16; nt++) {
            int col = nt * 8 + tig * 2;
            *(float2*)(o + col) = make_float2(acc[nt][half * 2] * inv,
                                              acc[nt][half * 2 + 1] * inv);
        }
    }
}

// ============================================================================
// kernel_launch
// ============================================================================
extern "C" void kernel_launch(void* const* d_in, const int* in_sizes, int n_in,
                              void* d_out, int out_size)
{
    const float* x  = (const float*)d_in[0];
    const float* wq = (const float*)d_in[1];
    const float* wk = (const float*)d_in[2];
    const float* wv = (const float*)d_in[3];
    const float* wo = (const float*)d_in[4];
    float* out = (float*)d_out;

    float *Q, *K, *V, *ATT;
    cudaGetSymbolAddress((void**)&Q,   g_Q);
    cudaGetSymbolAddress((void**)&K,   g_K);
    cudaGetSymbolAddress((void**)&V,   g_V);
    cudaGetSymbolAddress((void**)&ATT, g_attn);

    __nv_bfloat16 *xh, *xl, *wqh, *wql, *wkh, *wkl, *wvh, *wvl, *woh, *wol, *ah, *al;
    __nv_bfloat16 *qbh, *qbl, *kbh, *kbl, *vbh, *vbl;
    cudaGetSymbolAddress((void**)&xh,  g_xh);  cudaGetSymbolAddress((void**)&xl,  g_xl);
    cudaGetSymbolAddress((void**)&wqh, g_wqh); cudaGetSymbolAddress((void**)&wql, g_wql);
    cudaGetSymbolAddress((void**)&wkh, g_wkh); cudaGetSymbolAddress((void**)&wkl, g_wkl);
    cudaGetSymbolAddress((void**)&wvh, g_wvh); cudaGetSymbolAddress((void**)&wvl, g_wvl);
    cudaGetSymbolAddress((void**)&woh, g_woh); cudaGetSymbolAddress((void**)&wol, g_wol);
    cudaGetSymbolAddress((void**)&ah,  g_ah);  cudaGetSymbolAddress((void**)&al,  g_al);
    cudaGetSymbolAddress((void**)&qbh, g_qbh); cudaGetSymbolAddress((void**)&qbl, g_qbl);
    cudaGetSymbolAddress((void**)&kbh, g_kbh); cudaGetSymbolAddress((void**)&kbl, g_kbl);
    cudaGetSymbolAddress((void**)&vbh, g_vbh); cudaGetSymbolAddress((void**)&vbl, g_vbl);

    cudaFuncSetAttribute(gemm_bf16x3,
                         cudaFuncAttributeMaxDynamicSharedMemorySize, GSMEM);
    cudaFuncSetAttribute(attn_mma,
                         cudaFuncAttributeMaxDynamicSharedMemorySize, ASMEM);

    // 1) split x; transpose+split weights
    split_kernel<<<(SEQ * DIM / 4 + 255) / 256, 256>>>(x, xh, xl, SEQ * DIM / 4);
    transpose_split_kernel<<<dim3(DIM   / 32, DIM / 32), dim3(32, 8)>>>(wq, wqh, wql, DIM, DIM);
    transpose_split_kernel<<<dim3(KVDIM / 32, DIM / 32), dim3(32, 8)>>>(wk, wkh, wkl, DIM, KVDIM);
    transpose_split_kernel<<<dim3(KVDIM / 32, DIM / 32), dim3(32, 8)>>>(wv, wvh, wvl, DIM, KVDIM);
    transpose_split_kernel<<<dim3(DIM   / 32, DIM / 32), dim3(32, 8)>>>(wo, woh, wol, DIM, DIM);

    // 2) QKV projections (tensor cores)
    gemm_bf16x3<<<dim3(DIM   / GBN, SEQ / GBM), 256, GSMEM>>>(xh, xl, wqh, wql, Q, SEQ, DIM,   DIM);
    gemm_bf16x3<<<dim3(KVDIM / GBN, SEQ / GBM), 256, GSMEM>>>(xh, xl, wkh, wkl, K, SEQ, KVDIM, DIM);
    gemm_bf16x3<<<dim3(KVDIM / GBN, SEQ / GBM), 256, GSMEM>>>(xh, xl, wvh, wvl, V, SEQ, KVDIM, DIM);

    // 3) RoPE + bf16 split (fold 1/sqrt(HD) into Q); plain split for V
    const float scale = 0.08838834764831845f;
    int nq = SEQ * NH  * (HD / 2);
    int nk = SEQ * NKV * (HD / 2);
    rope_split_kernel<<<(nq + 255) / 256, 256>>>(Q, qbh, qbl, NH,  scale);
    rope_split_kernel<<<(nk + 255) / 256, 256>>>(K, kbh, kbl, NKV, 1.0f);
    split_kernel<<<(SEQ * KVDIM / 4 + 255) / 256, 256>>>(V, vbh, vbl, SEQ * KVDIM / 4);

    // 4) tensor-core attention
    attn_mma<<<dim3(SEQ / 64, NH), 128, ASMEM>>>(qbh, qbl, kbh, kbl, vbh, vbl);

    // 5) output projection
    split_kernel<<<(SEQ * DIM / 4 + 255) / 256, 256>>>(ATT, ah, al, SEQ * DIM / 4);
    gemm_bf16x3<<<dim3(DIM / GBN, SEQ / GBM), 256, GSMEM>>>(ah, al, woh, wol, out, SEQ, DIM, DIM);
}

// round 11
// speedup vs baseline: 1.3273x; 1.0024x over previous
#include <cuda_runtime.h>
#include <cuda_bf16.h>
#include <math.h>

// Problem constants
#define SEQ   2048
#define DIM   4096
#define NH    32
#define NKV   8
#define HD    128
#define KVDIM (NKV * HD)   // 1024

typedef unsigned int u32;

// -------- fp32 scratch --------
__device__ float g_Q[SEQ * DIM];
__device__ float g_K[SEQ * KVDIM];
__device__ float g_V[SEQ * KVDIM];
__device__ float g_attn[SEQ * DIM];

// -------- bf16 split operands (hi + lo residual) --------
__device__ __nv_bfloat16 g_xh[SEQ * DIM],    g_xl[SEQ * DIM];
__device__ __nv_bfloat16 g_wqh[DIM * DIM],   g_wql[DIM * DIM];     // transposed [N][K]
__device__ __nv_bfloat16 g_wkh[KVDIM * DIM], g_wkl[KVDIM * DIM];
__device__ __nv_bfloat16 g_wvh[KVDIM * DIM], g_wvl[KVDIM * DIM];
__device__ __nv_bfloat16 g_woh[DIM * DIM],   g_wol[DIM * DIM];
__device__ __nv_bfloat16 g_ah[SEQ * DIM],    g_al[SEQ * DIM];
// bf16 split Q/K/V for tensor-core attention
__device__ __nv_bfloat16 g_qbh[SEQ * DIM],   g_qbl[SEQ * DIM];
__device__ __nv_bfloat16 g_kbh[SEQ * KVDIM], g_kbl[SEQ * KVDIM];
__device__ __nv_bfloat16 g_vbh[SEQ * KVDIM], g_vbl[SEQ * KVDIM];

// ============================================================================
// Split fp32 -> bf16 hi + bf16 lo(residual). Vectorized x4.
// ============================================================================
__global__ void split_kernel(const float* __restrict__ in,
                             __nv_bfloat16* __restrict__ hi,
                             __nv_bfloat16* __restrict__ lo, int n4)
{
    int i = blockIdx.x * blockDim.x + threadIdx.x;
    if (i >= n4) return;
    float4 v = ((const float4*)in)[i];
    __nv_bfloat162 h01, h23, l01, l23;
    h01.x = __float2bfloat16(v.x); h01.y = __float2bfloat16(v.y);
    h23.x = __float2bfloat16(v.z); h23.y = __float2bfloat16(v.w);
    l01.x = __float2bfloat16(v.x - __bfloat162float(h01.x));
    l01.y = __float2bfloat16(v.y - __bfloat162float(h01.y));
    l23.x = __float2bfloat16(v.z - __bfloat162float(h23.x));
    l23.y = __float2bfloat16(v.w - __bfloat162float(h23.y));
    ((__nv_bfloat162*)hi)[2 * i]     = h01;
    ((__nv_bfloat162*)hi)[2 * i + 1] = h23;
    ((__nv_bfloat162*)lo)[2 * i]     = l01;
    ((__nv_bfloat162*)lo)[2 * i + 1] = l23;
}

// ============================================================================
// Transpose + split: in fp32 [K][N] -> hi/lo bf16 [N][K].
// ============================================================================
__global__ void transpose_split_kernel(const float* __restrict__ in,
                                       __nv_bfloat16* __restrict__ hi,
                                       __nv_bfloat16* __restrict__ lo,
                                       int K, int N)
{
    __shared__ float t[32][33];
    int n0 = blockIdx.x * 32, k0 = blockIdx.y * 32;
    int tx = threadIdx.x, ty = threadIdx.y;   // (32, 8)
    #pragma unroll
    for (int i = 0; i < 4; i++)
        t[ty + i * 8][tx] = in[(size_t)(k0 + ty + i * 8) * N + n0 + tx];
    __syncthreads();
    #pragma unroll
    for (int i = 0; i < 4; i++) {
        float v = t[tx][ty + i * 8];
        __nv_bfloat16 h = __float2bfloat16(v);
        size_t o = (size_t)(n0 + ty + i * 8) * K + k0 + tx;
        hi[o] = h;
        lo[o] = __float2bfloat16(v - __bfloat162float(h));
    }
}

// ============================================================================
// MMA / ldmatrix / cp.async primitives
// ============================================================================
__device__ __forceinline__ void ldsm4(u32* r, u32 addr) {
    asm volatile("ldmatrix.sync.aligned.m8n8.x4.shared.b16 {%0,%1,%2,%3}, [%4];\n"
        : "=r"(r[0]), "=r"(r[1]), "=r"(r[2]), "=r"(r[3]) : "r"(addr));
}
__device__ __forceinline__ void ldsm4t(u32* r, u32 addr) {
    asm volatile("ldmatrix.sync.aligned.m8n8.x4.trans.shared.b16 {%0,%1,%2,%3}, [%4];\n"
        : "=r"(r[0]), "=r"(r[1]), "=r"(r[2]), "=r"(r[3]) : "r"(addr));
}
__device__ __forceinline__ void mma16816(float* c, const u32* a, const u32* b) {
    asm volatile("mma.sync.aligned.m16n8k16.row.col.f32.bf16.bf16.f32 "
        "{%0,%1,%2,%3}, {%4,%5,%6,%7}, {%8,%9}, {%0,%1,%2,%3};\n"
        : "+f"(c[0]), "+f"(c[1]), "+f"(c[2]), "+f"(c[3])
        : "r"(a[0]), "r"(a[1]), "r"(a[2]), "r"(a[3]), "r"(b[0]), "r"(b[1]));
}
__device__ __forceinline__ void cp16(u32 dst, const void* src) {
    asm volatile("cp.async.cg.shared.global [%0], [%1], 16;\n" :: "r"(dst), "l"(src));
}

// ============================================================================
// bf16x3-split tensor-core GEMM (unchanged from R8 passing version)
// ============================================================================
#define GBM   128
#define GBN   128
#define GBK   32
#define GLD   40
#define GTILE (GBM * GLD)
#define GTILEB (GTILE * 2)
#define GSMEM (8 * GTILEB)

__global__ __launch_bounds__(256) void gemm_bf16x3(
    const __nv_bfloat16* __restrict__ Ah, const __nv_bfloat16* __restrict__ Al,
    const __nv_bfloat16* __restrict__ Bh, const __nv_bfloat16* __restrict__ Bl,
    float* __restrict__ C, int M, int N, int K)
{
    extern __shared__ __nv_bfloat16 smg[];
    __nv_bfloat16* sAh = smg;
    __nv_bfloat16* sAl = sAh + 2 * GTILE;
    __nv_bfloat16* sBh = sAl + 2 * GTILE;
    __nv_bfloat16* sBl = sBh + 2 * GTILE;

    const int tid  = threadIdx.x;
    const int lane = tid & 31;
    const int warp = tid >> 5;
    const int wm   = warp & 3;
    const int wn   = warp >> 2;
    const int m0   = blockIdx.y * GBM;
    const int n0   = blockIdx.x * GBN;

    const u32 sAh0 = (u32)__cvta_generic_to_shared(sAh);
    const u32 sAl0 = (u32)__cvta_generic_to_shared(sAl);
    const u32 sBh0 = (u32)__cvta_generic_to_shared(sBh);
    const u32 sBl0 = (u32)__cvta_generic_to_shared(sBl);

    const int lrow = tid >> 2;
    const int lkc  = (tid & 3) * 8;
    const size_t gA = (size_t)(m0 + lrow) * K + lkc;
    const size_t gB = (size_t)(n0 + lrow) * K + lkc;
    const u32 sOff  = (u32)(lrow * GLD + lkc) * 2;
    const u32 sOff2 = sOff + 64 * GLD * 2;

    float acc[2][8][4];
    #pragma unroll
    for (int a = 0; a < 2; a++)
        #pragma unroll
        for (int b = 0; b < 8; b++)
            #pragma unroll
            for (int c = 0; c < 4; c++) acc[a][b][c] = 0.f;

    const u32 aOff = (u32)((wm * 32 + (lane & 15)) * GLD + (lane >> 4) * 8) * 2;
    const u32 bOff = (u32)((wn * 64 + (lane & 7) + ((lane >> 4) & 1) * 8) * GLD
                           + ((lane >> 3) & 1) * 8) * 2;

    const int nk = K / GBK;

    {
        cp16(sAh0 + sOff,  Ah + gA);  cp16(sAh0 + sOff2, Ah + gA + (size_t)64 * K);
        cp16(sAl0 + sOff,  Al + gA);  cp16(sAl0 + sOff2, Al + gA + (size_t)64 * K);
        cp16(sBh0 + sOff,  Bh + gB);  cp16(sBh0 + sOff2, Bh + gB + (size_t)64 * K);
        cp16(sBl0 + sOff,  Bl + gB);  cp16(sBl0 + sOff2, Bl + gB + (size_t)64 * K);
        asm volatile("cp.async.commit_group;\n");
    }

    for (int it = 0; it < nk; it++) {
        if (it + 1 < nk) {
            const int kk = (it + 1) * GBK;
            const u32 sb = (u32)(((it + 1) & 1) * GTILEB);
            cp16(sAh0 + sb + sOff,  Ah + gA + kk);
            cp16(sAh0 + sb + sOff2, Ah + gA + kk + (size_t)64 * K);
            cp16(sAl0 + sb + sOff,  Al + gA + kk);
            cp16(sAl0 + sb + sOff2, Al + gA + kk + (size_t)64 * K);
            cp16(sBh0 + sb + sOff,  Bh + gB + kk);
            cp16(sBh0 + sb + sOff2, Bh + gB + kk + (size_t)64 * K);
            cp16(sBl0 + sb + sOff,  Bl + gB + kk);
            cp16(sBl0 + sb + sOff2, Bl + gB + kk + (size_t)64 * K);
            asm volatile("cp.async.commit_group;\n");
            asm volatile("cp.async.wait_group 1;\n");
        } else {
            asm volatile("cp.async.wait_group 0;\n");
        }
        __syncthreads();

        const u32 sb = (u32)((it & 1) * GTILEB);
        #pragma unroll
        for (int ks = 0; ks < 2; ks++) {
            const u32 kb = sb + ks * 32;
            u32 a_hi[2][4], a_lo[2][4], b_hi[4][4], b_lo[4][4];
            #pragma unroll
            for (int mt = 0; mt < 2; mt++) {
                ldsm4(a_hi[mt], sAh0 + kb + aOff + mt * (16 * GLD * 2));
                ldsm4(a_lo[mt], sAl0 + kb + aOff + mt * (16 * GLD * 2));
            }
            #pragma unroll
            for (int np = 0; np < 4; np++) {
                ldsm4(b_hi[np], sBh0 + kb + bOff + np * (16 * GLD * 2));
                ldsm4(b_lo[np], sBl0 + kb + bOff + np * (16 * GLD * 2));
            }
            #pragma unroll
            for (int mt = 0; mt < 2; mt++)
                #pragma unroll
                for (int nt = 0; nt < 8; nt++) {
                    const u32* bh = &b_hi[nt >> 1][(nt & 1) * 2];
                    const u32* bl = &b_lo[nt >> 1][(nt & 1) * 2];
                    mma16816(acc[mt][nt], a_hi[mt], bh);
                    mma16816(acc[mt][nt], a_lo[mt], bh);
                    mma16816(acc[mt][nt], a_hi[mt], bl);
                }
        }
        __syncthreads();
    }

    const int erow = m0 + wm * 32 + (lane >> 2);
    const int ecol = n0 + wn * 64 + (lane & 3) * 2;
    #pragma unroll
    for (int mt = 0; mt < 2; mt++)
        #pragma unroll
        for (int nt = 0; nt < 8; nt++) {
            int r = erow + mt * 16;
            int c = ecol + nt * 8;
            *(float2*)&C[(size_t)r * N + c] =
                make_float2(acc[mt][nt][0], acc[mt][nt][1]);
            *(float2*)&C[(size_t)(r + 8) * N + c] =
                make_float2(acc[mt][nt][2], acc[mt][nt][3]);
        }
}

// ============================================================================
// RoPE + bf16 hi/lo split: reads fp32 [SEQ][n_heads][128], writes split bf16.
// ============================================================================
__global__ void rope_split_kernel(const float* __restrict__ src,
                                  __nv_bfloat16* __restrict__ hi,
                                  __nv_bfloat16* __restrict__ lo,
                                  int n_heads, float scale)
{
    int idx = blockIdx.x * blockDim.x + threadIdx.x;
    int total = SEQ * n_heads * (HD / 2);
    if (idx >= total) return;
    int i   = idx & 63;
    int h   = (idx >> 6) % n_heads;
    int pos = idx / (64 * n_heads);

    float inv = powf(10000.0f, -(float)(2 * i) / 128.0f);
    float ang = (float)pos * inv;
    float s, c;
    sincosf(ang, &s, &c);

    size_t off = ((size_t)pos * n_heads + h) * HD + 2 * i;
    const float* p = src + off;
    float a = p[0], b = p[1];
    float o0 = (a * c - b * s) * scale;
    float o1 = (a * s + b * c) * scale;

    __nv_bfloat162 hh, ll;
    hh.x = __float2bfloat16(o0);
    hh.y = __float2bfloat16(o1);
    ll.x = __float2bfloat16(o0 - __bfloat162float(hh.x));
    ll.y = __float2bfloat16(o1 - __bfloat162float(hh.y));
    ((__nv_bfloat162*)hi)[off >> 1] = hh;
    ((__nv_bfloat162*)lo)[off >> 1] = ll;
}

// ============================================================================
// Tensor-core flash attention (causal, GQA), bf16x3-split.
// grid = (SEQ/64, NH), 128 threads (4 warps, warp w owns q-rows w*16..+15).
// S = Qh*Kh + Ql*Kh + Qh*Kl; P split into hi/lo in registers (FA2 reuse);
// O += Ph*Vh + Pl*Vh + Ph*Vl.  V loaded via ldmatrix.trans.
// ============================================================================
#define LDB   136                     // bf16 row stride (128 + 8 pad)
#define ATILE (64 * LDB)              // elems per smem tile
#define ASMEM (6 * ATILE * 2)         // 6 tiles (Qh,Ql,Kh,Kl,Vh,Vl) = 104448 B

__global__ __launch_bounds__(128) void attn_mma(
    const __nv_bfloat16* __restrict__ Qh, const __nv_bfloat16* __restrict__ Ql,
    const __nv_bfloat16* __restrict__ Kh, const __nv_bfloat16* __restrict__ Kl,
    const __nv_bfloat16* __restrict__ Vh, const __nv_bfloat16* __restrict__ Vl)
{
    extern __shared__ __nv_bfloat16 sma[];
    const u32 sQh = (u32)__cvta_generic_to_shared(sma);
    const u32 sQl = sQh + ATILE * 2;
    const u32 sKh = sQl + ATILE * 2;
    const u32 sKl = sKh + ATILE * 2;
    const u32 sVh = sKl + ATILE * 2;
    const u32 sVl = sVh + ATILE * 2;

    const int tid  = threadIdx.x;
    const int lane = tid & 31;
    const int warp = tid >> 5;
    const int qb   = blockIdx.x;
    const int h    = blockIdx.y;
    const int kvh  = h >> 2;            // N_REP = 4
    const int g    = lane >> 2;         // row-in-fragment 0..7
    const int tig  = lane & 3;          // thread-in-group

    // ---- loader geometry: row = tid>>1, half = tid&1 (64 bf16 = 8 x 16B) ----
    const int lrow  = tid >> 1;
    const int lhalf = (tid & 1) * 64;
    const u32 sOff  = (u32)(lrow * LDB + lhalf) * 2;

    // Q tile (persistent in smem)
    {
        size_t qo = ((size_t)(qb * 64 + lrow) * NH + h) * HD + lhalf;
        #pragma unroll
        for (int c = 0; c < 8; c++) {
            cp16(sQh + sOff + c * 16, Qh + qo + c * 8);
            cp16(sQl + sOff + c * 16, Ql + qo + c * 8);
        }
        asm volatile("cp.async.commit_group;\n");
    }

    // ---- fragment addresses ----
    const u32 aO = (u32)((warp * 16 + (lane & 15)) * LDB) * 2 + (lane >> 4) * 16;
    const u32 bO = (u32)(((lane & 7) + ((lane >> 4) & 1) * 8) * LDB) * 2
                 + ((lane >> 3) & 1) * 16;
    const u32 vO = (u32)((lane & 15) * LDB) * 2 + (lane >> 4) * 16;

    float m[2] = {-1e30f, -1e30f}, l[2] = {0.f, 0.f};
    float acc[16][4];
    #pragma unroll
    for (int nt = 0; nt < 16; nt++)
        #pragma unroll
        for (int c = 0; c < 4; c++) acc[nt][c] = 0.f;

    for (int j = 0; j <= qb; j++) {
        __syncthreads();   // previous iteration's K/V reads complete
        {
            size_t ko = ((size_t)(j * 64 + lrow) * NKV + kvh) * HD + lhalf;
            #pragma unroll
            for (int c = 0; c < 8; c++) {
                cp16(sKh + sOff + c * 16, Kh + ko + c * 8);
                cp16(sKl + sOff + c * 16, Kl + ko + c * 8);
                cp16(sVh + sOff + c * 16, Vh + ko + c * 8);
                cp16(sVl + sOff + c * 16, Vl + ko + c * 8);
            }
            asm volatile("cp.async.commit_group;\n");
            asm volatile("cp.async.wait_group 0;\n");
        }
        __syncthreads();

        // ---- S = Q @ K^T (bf16x3), per-warp m16 x n64, k = 128 ----
        float sv[8][4];
        #pragma unroll
        for (int nt = 0; nt < 8; nt++)
            #pragma unroll
            for (int c = 0; c < 4; c++) sv[nt][c] = 0.f;

        #pragma unroll
        for (int ks = 0; ks < 8; ks++) {
            const u32 kb = ks * 32;
            u32 ah[4], al[4];
            ldsm4(ah, sQh + aO + kb);
            ldsm4(al, sQl + aO + kb);
            #pragma unroll
            for (int np = 0; np < 4; np++) {
                u32 bh[4], bl[4];
                ldsm4(bh, sKh + bO + np * (16 * LDB * 2) + kb);
                ldsm4(bl, sKl + bO + np * (16 * LDB * 2) + kb);
                mma16816(sv[2 * np],     ah, &bh[0]);
                mma16816(sv[2 * np],     al, &bh[0]);
                mma16816(sv[2 * np],     ah, &bl[0]);
                mma16816(sv[2 * np + 1], ah, &bh[2]);
                mma16816(sv[2 * np + 1], al, &bh[2]);
                mma16816(sv[2 * np + 1], ah, &bl[2]);
            }
        }

        // ---- causal mask on diagonal block ----
        if (j == qb) {
            #pragma unroll
            for (int nt = 0; nt < 8; nt++)
                #pragma unroll
                for (int c = 0; c < 4; c++) {
                    int col = nt * 8 + tig * 2 + (c & 1);
                    int row = warp * 16 + g + (c >> 1) * 8;
                    if (col > row) sv[nt][c] = -1e30f;
                }
        }

        // ---- online softmax (rows g and g+8; groups of 4 lanes per row) ----
        #pragma unroll
        for (int half = 0; half < 2; half++) {
            float rm = -1e30f;
            #pragma unroll
            for (int nt = 0; nt < 8; nt++)
                rm = fmaxf(rm, fmaxf(sv[nt][half * 2], sv[nt][half * 2 + 1]));
            rm = fmaxf(rm, __shfl_xor_sync(0xffffffffu, rm, 1));
            rm = fmaxf(rm, __shfl_xor_sync(0xffffffffu, rm, 2));
            float mn   = fmaxf(m[half], rm);
            float corr = __expf(m[half] - mn);
            float rs = 0.f;
            #pragma unroll
            for (int nt = 0; nt < 8; nt++) {
                float p0 = __expf(sv[nt][half * 2]     - mn);
                float p1 = __expf(sv[nt][half * 2 + 1] - mn);
                sv[nt][half * 2]     = p0;
                sv[nt][half * 2 + 1] = p1;
                rs += p0 + p1;
            }
            rs += __shfl_xor_sync(0xffffffffu, rs, 1);
            rs += __shfl_xor_sync(0xffffffffu, rs, 2);
            l[half] = l[half] * corr + rs;
            m[half] = mn;
            #pragma unroll
            for (int nt = 0; nt < 16; nt++) {
                acc[nt][half * 2]     *= corr;
                acc[nt][half * 2 + 1] *= corr;
            }
        }
        __syncwarp();

        // ---- O += P @ V (bf16x3), P fragments built from sv in registers ----
        #pragma unroll
        for (int ks = 0; ks < 4; ks++) {
            u32 pa_h[4], pa_l[4];
            #pragma unroll
            for (int t = 0; t < 2; t++) {
                float p0 = sv[2 * ks + t][0], p1 = sv[2 * ks + t][1];
                float p2 = sv[2 * ks + t][2], p3 = sv[2 * ks + t][3];
                __nv_bfloat162 h01, h23, l01, l23;
                h01.x = __float2bfloat16(p0); h01.y = __float2bfloat16(p1);
                h23.x = __float2bfloat16(p2); h23.y = __float2bfloat16(p3);
                l01.x = __float2bfloat16(p0 - __bfloat162float(h01.x));
                l01.y = __float2bfloat16(p1 - __bfloat162float(h01.y));
                l23.x = __float2bfloat16(p2 - __bfloat162float(h23.x));
                l23.y = __float2bfloat16(p3 - __bfloat162float(h23.y));
                pa_h[2 * t]     = *(u32*)&h01;  // a0/a2: row g
                pa_h[2 * t + 1] = *(u32*)&h23;  // a1/a3: row g+8
                pa_l[2 * t]     = *(u32*)&l01;
                pa_l[2 * t + 1] = *(u32*)&l23;
            }
            const u32 kb = (u32)(ks * 16 * LDB) * 2;
            #pragma unroll
            for (int np = 0; np < 8; np++) {
                u32 vh[4], vl[4];
                ldsm4t(vh, sVh + vO + kb + np * 32);
                ldsm4t(vl, sVl + vO + kb + np * 32);
                mma16816(acc[2 * np],     pa_h, &vh[0]);
                mma16816(acc[2 * np],     pa_l, &vh[0]);
                mma16816(acc[2 * np],     pa_h, &vl[0]);
                mma16816(acc[2 * np + 1], pa_h, &vh[2]);
                mma16816(acc[2 * np + 1], pa_l, &vh[2]);
                mma16816(acc[2 * np + 1], pa_h, &vl[2]);
            }
        }
    }

    // ---- epilogue: normalize, write fp32 [SEQ][NH*HD] ----
    #pragma unroll
    for (int half = 0; half < 2; half++) {
        float inv = 1.0f / l[half];
        int row = qb * 64 + warp * 16 + g + half * 8;
        float* o = g_attn + (size_t)row * DIM + h * HD;
        #pragma unroll
        for (int nt = 0; nt < 16; nt++) {
            int col = nt * 8 + tig * 2;
            *(float2*)(o + col) = make_float2(acc[nt][half * 2] * inv,
                                              acc[nt][half * 2 + 1] * inv);
        }
    }
}

// ============================================================================
// kernel_launch
// ============================================================================
extern "C" void kernel_launch(void* const* d_in, const int* in_sizes, int n_in,
                              void* d_out, int out_size)
{
    const float* x  = (const float*)d_in[0];
    const float* wq = (const float*)d_in[1];
    const float* wk = (const float*)d_in[2];
    const float* wv = (const float*)d_in[3];
    const float* wo = (const float*)d_in[4];
    float* out = (float*)d_out;

    float *Q, *K, *V, *ATT;
    cudaGetSymbolAddress((void**)&Q,   g_Q);
    cudaGetSymbolAddress((void**)&K,   g_K);
    cudaGetSymbolAddress((void**)&V,   g_V);
    cudaGetSymbolAddress((void**)&ATT, g_attn);

    __nv_bfloat16 *xh, *xl, *wqh, *wql, *wkh, *wkl, *wvh, *wvl, *woh, *wol, *ah, *al;
    __nv_bfloat16 *qbh, *qbl, *kbh, *kbl, *vbh, *vbl;
    cudaGetSymbolAddress((void**)&xh,  g_xh);  cudaGetSymbolAddress((void**)&xl,  g_xl);
    cudaGetSymbolAddress((void**)&wqh, g_wqh); cudaGetSymbolAddress((void**)&wql, g_wql);
    cudaGetSymbolAddress((void**)&wkh, g_wkh); cudaGetSymbolAddress((void**)&wkl, g_wkl);
    cudaGetSymbolAddress((void**)&wvh, g_wvh); cudaGetSymbolAddress((void**)&wvl, g_wvl);
    cudaGetSymbolAddress((void**)&woh, g_woh); cudaGetSymbolAddress((void**)&wol, g_wol);
    cudaGetSymbolAddress((void**)&ah,  g_ah);  cudaGetSymbolAddress((void**)&al,  g_al);
    cudaGetSymbolAddress((void**)&qbh, g_qbh); cudaGetSymbolAddress((void**)&qbl, g_qbl);
    cudaGetSymbolAddress((void**)&kbh, g_kbh); cudaGetSymbolAddress((void**)&kbl, g_kbl);
    cudaGetSymbolAddress((void**)&vbh, g_vbh); cudaGetSymbolAddress((void**)&vbl, g_vbl);

    cudaFuncSetAttribute(gemm_bf16x3,
                         cudaFuncAttributeMaxDynamicSharedMemorySize, GSMEM);
    cudaFuncSetAttribute(attn_mma,
                         cudaFuncAttributeMaxDynamicSharedMemorySize, ASMEM);

    // 1) split x; transpose+split weights
    split_kernel<<<(SEQ * DIM / 4 + 255) / 256, 256>>>(x, xh, xl, SEQ * DIM / 4);
    transpose_split_kernel<<<dim3(DIM   / 32, DIM / 32), dim3(32, 8)>>>(wq, wqh, wql, DIM, DIM);
    transpose_split_kernel<<<dim3(KVDIM / 32, DIM / 32), dim3(32, 8)>>>(wk, wkh, wkl, DIM, KVDIM);
    transpose_split_kernel<<<dim3(KVDIM / 32, DIM / 32), dim3(32, 8)>>>(wv, wvh, wvl, DIM, KVDIM);
    transpose_split_kernel<<<dim3(DIM   / 32, DIM / 32), dim3(32, 8)>>>(wo, woh, wol, DIM, DIM);

    // 2) QKV projections (tensor cores)
    gemm_bf16x3<<<dim3(DIM   / GBN, SEQ / GBM), 256, GSMEM>>>(xh, xl, wqh, wql, Q, SEQ, DIM,   DIM);
    gemm_bf16x3<<<dim3(KVDIM / GBN, SEQ / GBM), 256, GSMEM>>>(xh, xl, wkh, wkl, K, SEQ, KVDIM, DIM);
    gemm_bf16x3<<<dim3(KVDIM / GBN, SEQ / GBM), 256, GSMEM>>>(xh, xl, wvh, wvl, V, SEQ, KVDIM, DIM);

    // 3) RoPE + bf16 split (fold 1/sqrt(HD) into Q); plain split for V
    const float scale = 0.08838834764831845f;
    int nq = SEQ * NH  * (HD / 2);
    int nk = SEQ * NKV * (HD / 2);
    rope_split_kernel<<<(nq + 255) / 256, 256>>>(Q, qbh, qbl, NH,  scale);
    rope_split_kernel<<<(nk + 255) / 256, 256>>>(K, kbh, kbl, NKV, 1.0f);
    split_kernel<<<(SEQ * KVDIM / 4 + 255) / 256, 256>>>(V, vbh, vbl, SEQ * KVDIM / 4);

    // 4) tensor-core attention
    attn_mma<<<dim3(SEQ / 64, NH), 128, ASMEM>>>(qbh, qbl, kbh, kbl, vbh, vbl);

    // 5) output projection
    split_kernel<<<(SEQ * DIM / 4 + 255) / 256, 256>>>(ATT, ah, al, SEQ * DIM / 4);
    gemm_bf16x3<<<dim3(DIM / GBN, SEQ / GBM), 256, GSMEM>>>(ah, al, woh, wol, out, SEQ, DIM, DIM);
}